// round 6
// baseline (speedup 1.0000x reference)
#include <cuda_runtime.h>

#define BATCH 16
#define NROW  16384
#define DIM   128
#define KPT   10
#define SROWS 256                 // rows per score block
#define NBLK  64                  // 16384 / 256
#define NPART 256                 // NBLK * 4 warps
#define CCOLS 32                  // d-columns per staged chunk
#define NC 4                      // 128 / 32
#define TSTRIDE 36                // words per row in smem tile (144B; 4*lane%32 conflict-free)
#define SCALE_F 0.08838834764831843f  // 1/sqrt(128)

// ---------------- scratch (static device memory: allowed) ----------------
__device__ float g_colsum[2][BATCH][16][DIM];
__device__ float g_hbar[2][BATCH][DIM];
__device__ float g_v[2][BATCH][KPT][DIM];
__device__ float g_part[2][BATCH][KPT][NPART][5];
__device__ float g_Y[2][BATCH][KPT][3];

// ---------------- pass 1: column sums of H1/H2 (fp32) ----------------
__global__ void mean_kernel(const float* __restrict__ H1, const float* __restrict__ H2) {
    int chunk = blockIdx.x, b = blockIdx.y, side = blockIdx.z;
    const float* H = side ? H2 : H1;
    int t = threadIdx.x;
    int col4 = t & 31, rl = t >> 5;
    const float4* base = (const float4*)(H + ((size_t)b * NROW + (size_t)chunk * 1024) * DIM);
    float s0 = 0.f, s1 = 0.f, s2 = 0.f, s3 = 0.f;
#pragma unroll 8
    for (int r = rl; r < 1024; r += 8) {
        float4 v = base[(size_t)r * 32 + col4];
        s0 += v.x; s1 += v.y; s2 += v.z; s3 += v.w;
    }
    __shared__ float red[256][4];
    red[t][0] = s0; red[t][1] = s1; red[t][2] = s2; red[t][3] = s3;
    __syncthreads();
    if (t < 32) {
        float a0 = red[t][0], a1 = red[t][1], a2 = red[t][2], a3 = red[t][3];
#pragma unroll
        for (int m = 1; m < 8; m++) {
            a0 += red[t + 32 * m][0]; a1 += red[t + 32 * m][1];
            a2 += red[t + 32 * m][2]; a3 += red[t + 32 * m][3];
        }
        float* o = &g_colsum[side][b][chunk][t * 4];
        o[0] = a0; o[1] = a1; o[2] = a2; o[3] = a3;
    }
}

__global__ void hbar_kernel() {
    int side = blockIdx.x, b = blockIdx.y, d = threadIdx.x;
    float s = 0.f;
#pragma unroll
    for (int c = 0; c < 16; c++) s += g_colsum[side][b][c][d];
    g_hbar[side][b][d] = s * (1.0f / NROW);
}

// v[side][b][k][d] = scale * sum_e W_side[k][d][e] * hbar[side^1][b][e]
__global__ void v_kernel(const float* __restrict__ W1, const float* __restrict__ W2) {
    int k = blockIdx.x, b = blockIdx.y, side = blockIdx.z;
    const float* W = side ? W2 : W1;
    __shared__ float hb[DIM];
    int d = threadIdx.x;
    hb[d] = g_hbar[side ^ 1][b][d];
    __syncthreads();
    const float4* wr = (const float4*)(W + ((size_t)k * DIM + d) * DIM);
    float acc = 0.f;
#pragma unroll 8
    for (int e4 = 0; e4 < 32; e4++) {
        float4 w = __ldg(&wr[e4]);
        acc += w.x * hb[e4 * 4 + 0] + w.y * hb[e4 * 4 + 1]
             + w.z * hb[e4 * 4 + 2] + w.w * hb[e4 * 4 + 3];
    }
    g_v[side][b][k][d] = acc * SCALE_F;
}

// ---------------- pass 2: scores + online softmax + weighted X sums ----------------
union U64F2 { unsigned long long u; float2 f; };

__device__ __forceinline__ void osm_combine(float& m, float& l, float& a0, float& a1, float& a2,
                                            float m2, float l2, float b0, float b1, float b2) {
    float mn = fmaxf(m, m2);
    float f1 = __expf(m - mn), f2 = __expf(m2 - mn);
    m = mn;
    l = l * f1 + l2 * f2;
    a0 = a0 * f1 + b0 * f2;
    a1 = a1 * f1 + b1 * f2;
    a2 = a2 * f1 + b2 * f2;
}

__global__ __launch_bounds__(128, 6) void score_kernel(
    const float* __restrict__ H1, const float* __restrict__ H2,
    const float* __restrict__ X1, const float* __restrict__ X2) {
    int chunk = blockIdx.x, b = blockIdx.y, side = blockIdx.z;
    const float* H = side ? H2 : H1;
    const float* X = side ? X2 : X1;
    int t = threadIdx.x;
    int row0 = chunk * SROWS;

    __shared__ float tile[SROWS * TSTRIDE];        // 36864 B (single buffer)

    const float* Hb = H + ((size_t)b * NROW + row0) * DIM;
    const float4* vg = (const float4*)&g_v[side][b][0][0];   // uniform, L1-resident

    unsigned long long accA[KPT], accB[KPT];
#pragma unroll
    for (int k = 0; k < KPT; k++) { accA[k] = 0ull; accB[k] = 0ull; }

    for (int c = 0; c < NC; c++) {
        __syncthreads();   // previous chunk's compute done before overwrite
        // stage 256 rows x 32 cols: coalesced LDG.128 (8 lanes cover a full 128B row-segment)
#pragma unroll
        for (int i = 0; i < 16; i++) {
            int idx = t + 128 * i;
            int r = idx >> 3, j = idx & 7;
            float4 val = *(const float4*)(Hb + (size_t)r * DIM + c * CCOLS + j * 4);
            *(float4*)&tile[r * TSTRIDE + j * 4] = val;
        }
        __syncthreads();

        const float* rowA = &tile[t * TSTRIDE];
        const float* rowB = &tile[(t + 128) * TSTRIDE];
#pragma unroll
        for (int j = 0; j < 8; j++) {
            ulonglong2 xa = *(const ulonglong2*)&rowA[j * 4];
            ulonglong2 xb = *(const ulonglong2*)&rowB[j * 4];
#pragma unroll
            for (int k = 0; k < KPT; k++) {
                // uniform global load: same address across warp -> 1 wavefront, L1 hit
                float4 vf = __ldg(&vg[(k * DIM + c * CCOLS) / 4 + j]);
                U64F2 v0, v1;
                v0.f = make_float2(vf.x, vf.y);
                v1.f = make_float2(vf.z, vf.w);
                asm("fma.rn.f32x2 %0, %1, %2, %0;" : "+l"(accA[k]) : "l"(xa.x), "l"(v0.u));
                asm("fma.rn.f32x2 %0, %1, %2, %0;" : "+l"(accA[k]) : "l"(xa.y), "l"(v1.u));
                asm("fma.rn.f32x2 %0, %1, %2, %0;" : "+l"(accB[k]) : "l"(xb.x), "l"(v0.u));
                asm("fma.rn.f32x2 %0, %1, %2, %0;" : "+l"(accB[k]) : "l"(xb.y), "l"(v1.u));
            }
        }
    }

    // per-thread rows: row0+t and row0+t+128
    const float* Xb = X + ((size_t)b * NROW + row0) * 3;
    float XA0 = Xb[t * 3 + 0], XA1 = Xb[t * 3 + 1], XA2 = Xb[t * 3 + 2];
    float XB0 = Xb[(t + 128) * 3 + 0], XB1 = Xb[(t + 128) * 3 + 1], XB2 = Xb[(t + 128) * 3 + 2];

    int w = t >> 5, lane = t & 31;
#pragma unroll
    for (int k = 0; k < KPT; k++) {
        U64F2 ua, ub;
        ua.u = accA[k]; ub.u = accB[k];
        float sA = ua.f.x + ua.f.y;
        float sB = ub.f.x + ub.f.y;
        float m = fmaxf(sA, sB);
        float eA = __expf(sA - m), eB = __expf(sB - m);
        float l = eA + eB;
        float a0 = eA * XA0 + eB * XB0;
        float a1 = eA * XA1 + eB * XB1;
        float a2 = eA * XA2 + eB * XB2;
#pragma unroll
        for (int off = 16; off > 0; off >>= 1) {
            float m2 = __shfl_xor_sync(0xffffffffu, m, off);
            float l2 = __shfl_xor_sync(0xffffffffu, l, off);
            float b0 = __shfl_xor_sync(0xffffffffu, a0, off);
            float b1 = __shfl_xor_sync(0xffffffffu, a1, off);
            float b2 = __shfl_xor_sync(0xffffffffu, a2, off);
            osm_combine(m, l, a0, a1, a2, m2, l2, b0, b1, b2);
        }
        if (lane == 0) {   // per-warp partial straight to gmem (no cross-warp smem reduce)
            float* o = &g_part[side][b][k][chunk * 4 + w][0];
            o[0] = m; o[1] = l; o[2] = a0; o[3] = a1; o[4] = a2;
        }
    }
}

// ---------------- combine partials -> Y ----------------
__global__ void combine_kernel() {
    int side = blockIdx.x, b = blockIdx.y;
    int k = threadIdx.x >> 5, lane = threadIdx.x & 31;
    const float* base = &g_part[side][b][k][0][0];
    const float* p = base + lane * 5;
    float m = p[0], l = p[1], a0 = p[2], a1 = p[3], a2 = p[4];
#pragma unroll
    for (int q = 1; q < NPART / 32; q++) {
        const float* p2 = base + (lane + 32 * q) * 5;
        osm_combine(m, l, a0, a1, a2, p2[0], p2[1], p2[2], p2[3], p2[4]);
    }
#pragma unroll
    for (int off = 16; off > 0; off >>= 1) {
        float m2 = __shfl_xor_sync(0xffffffffu, m, off);
        float l2 = __shfl_xor_sync(0xffffffffu, l, off);
        float b0 = __shfl_xor_sync(0xffffffffu, a0, off);
        float b1 = __shfl_xor_sync(0xffffffffu, a1, off);
        float b2 = __shfl_xor_sync(0xffffffffu, a2, off);
        osm_combine(m, l, a0, a1, a2, m2, l2, b0, b1, b2);
    }
    if (lane == 0) {
        float inv = 1.0f / l;
        g_Y[side][b][k][0] = a0 * inv;
        g_Y[side][b][k][1] = a1 * inv;
        g_Y[side][b][k][2] = a2 * inv;
    }
}

// ---------------- Kabsch (fp32, 3x3 Jacobi) ----------------
__global__ void kabsch_kernel(float* __restrict__ out) {
    int b = threadIdx.x;
    if (b >= BATCH) return;
    float P[KPT][3], Q[KPT][3];
    for (int k = 0; k < KPT; k++)
        for (int c = 0; c < 3; c++) {
            P[k][c] = g_Y[0][b][k][c];
            Q[k][c] = g_Y[1][b][k][c];
        }
    float c1[3] = {0, 0, 0}, c2[3] = {0, 0, 0};
    for (int k = 0; k < KPT; k++)
        for (int c = 0; c < 3; c++) { c1[c] += P[k][c]; c2[c] += Q[k][c]; }
    for (int c = 0; c < 3; c++) { c1[c] *= (1.0f / KPT); c2[c] *= (1.0f / KPT); }

    float Hm[3][3] = {{0,0,0},{0,0,0},{0,0,0}};
    for (int k = 0; k < KPT; k++)
        for (int i = 0; i < 3; i++)
            for (int j = 0; j < 3; j++)
                Hm[i][j] += (P[k][i] - c1[i]) * (Q[k][j] - c2[j]);

    float A[3][3];
    for (int i = 0; i < 3; i++)
        for (int j = 0; j < 3; j++) {
            float s = 0;
            for (int r = 0; r < 3; r++) s += Hm[r][i] * Hm[r][j];
            A[i][j] = s;
        }
    float V[3][3] = {{1,0,0},{0,1,0},{0,0,1}};
    for (int sweep = 0; sweep < 8; sweep++) {
        for (int pq = 0; pq < 3; pq++) {
            int p = (pq == 2) ? 1 : 0;
            int q = (pq == 0) ? 1 : 2;
            float apq = A[p][q];
            if (fabsf(apq) < 1e-35f) continue;
            float theta = (A[q][q] - A[p][p]) / (2.0f * apq);
            float tt = ((theta >= 0.f) ? 1.0f : -1.0f) / (fabsf(theta) + sqrtf(theta * theta + 1.0f));
            float cth = rsqrtf(tt * tt + 1.0f), sth = tt * cth;
            for (int i = 0; i < 3; i++) {
                float aip = A[i][p], aiq = A[i][q];
                A[i][p] = cth * aip - sth * aiq;
                A[i][q] = sth * aip + cth * aiq;
            }
            for (int i = 0; i < 3; i++) {
                float api = A[p][i], aqi = A[q][i];
                A[p][i] = cth * api - sth * aqi;
                A[q][i] = sth * api + cth * aqi;
            }
            for (int i = 0; i < 3; i++) {
                float vip = V[i][p], viq = V[i][q];
                V[i][p] = cth * vip - sth * viq;
                V[i][q] = sth * vip + cth * viq;
            }
        }
    }
    float w[3] = {A[0][0], A[1][1], A[2][2]};
    int idx[3] = {0, 1, 2};
    for (int i = 0; i < 2; i++)
        for (int j = i + 1; j < 3; j++)
            if (w[idx[j]] > w[idx[i]]) { int tmp = idx[i]; idx[i] = idx[j]; idx[j] = tmp; }
    float v0[3], v1[3], v2[3];
    for (int i = 0; i < 3; i++) {
        v0[i] = V[i][idx[0]]; v1[i] = V[i][idx[1]]; v2[i] = V[i][idx[2]];
    }
    float u0[3], u1[3], u2[3];
    for (int i = 0; i < 3; i++) {
        u0[i] = Hm[i][0] * v0[0] + Hm[i][1] * v0[1] + Hm[i][2] * v0[2];
        u1[i] = Hm[i][0] * v1[0] + Hm[i][1] * v1[1] + Hm[i][2] * v1[2];
    }
    float n0 = sqrtf(u0[0]*u0[0] + u0[1]*u0[1] + u0[2]*u0[2]);
    n0 = (n0 > 0.f) ? 1.0f / n0 : 0.0f;
    for (int i = 0; i < 3; i++) u0[i] *= n0;
    float d01 = u1[0]*u0[0] + u1[1]*u0[1] + u1[2]*u0[2];
    for (int i = 0; i < 3; i++) u1[i] -= d01 * u0[i];
    float n1 = sqrtf(u1[0]*u1[0] + u1[1]*u1[1] + u1[2]*u1[2]);
    n1 = (n1 > 0.f) ? 1.0f / n1 : 0.0f;
    for (int i = 0; i < 3; i++) u1[i] *= n1;
    u2[0] = u0[1]*u1[2] - u0[2]*u1[1];
    u2[1] = u0[2]*u1[0] - u0[0]*u1[2];
    u2[2] = u0[0]*u1[1] - u0[1]*u1[0];
    float cx = v1[1]*v2[2] - v1[2]*v2[1];
    float cy = v1[2]*v2[0] - v1[0]*v2[2];
    float cz = v1[0]*v2[1] - v1[1]*v2[0];
    float detV = v0[0]*cx + v0[1]*cy + v0[2]*cz;
    float s = (detV >= 0.f) ? 1.0f : -1.0f;

    float R[3][3];
    for (int i = 0; i < 3; i++)
        for (int j = 0; j < 3; j++)
            R[i][j] = u0[i]*v0[j] + u1[i]*v1[j] + s*u2[i]*v2[j];
    float tv[3];
    for (int j = 0; j < 3; j++)
        tv[j] = c2[j] - (c1[0]*R[0][j] + c1[1]*R[1][j] + c1[2]*R[2][j]);

    float* ob = out + b * 90;   // [3][K][3]
    for (int k = 0; k < KPT; k++)
        for (int c = 0; c < 3; c++) {
            ob[0 * 30 + k * 3 + c] = P[k][c];
            ob[1 * 30 + k * 3 + c] = Q[k][c];
        }
    for (int k = 0; k < KPT; k++)
        for (int j = 0; j < 3; j++) {
            float y = P[k][0]*R[0][j] + P[k][1]*R[1][j] + P[k][2]*R[2][j] + tv[j];
            ob[2 * 30 + k * 3 + j] = y;
        }
}

// ---------------- launch ----------------
extern "C" void kernel_launch(void* const* d_in, const int* in_sizes, int n_in,
                              void* d_out, int out_size) {
    const float* H1 = (const float*)d_in[0];
    const float* H2 = (const float*)d_in[1];
    const float* X1 = (const float*)d_in[2];
    const float* X2 = (const float*)d_in[3];
    const float* W1 = (const float*)d_in[4];
    const float* W2 = (const float*)d_in[5];
    float* out = (float*)d_out;

    mean_kernel<<<dim3(16, BATCH, 2), 256>>>(H1, H2);
    hbar_kernel<<<dim3(2, BATCH), DIM>>>();
    v_kernel<<<dim3(KPT, BATCH, 2), DIM>>>(W1, W2);
    score_kernel<<<dim3(NBLK, BATCH, 2), 128>>>(H1, H2, X1, X2);
    combine_kernel<<<dim3(2, BATCH), 320>>>();
    kabsch_kernel<<<1, 32>>>(out);
}

// round 7
// speedup vs baseline: 1.1240x; 1.1240x over previous
#include <cuda_runtime.h>

#define BATCH 16
#define NROW  16384
#define DIM   128
#define KPT   10
#define SROWS 256                 // rows per score block
#define NBLK  64                  // 16384 / 256
#define NPART 256                 // NBLK * 4 warps
#define CCOLS 32                  // d-columns per staged chunk
#define NC 4                      // 128 / 32
#define TSTRIDE 36                // words/row in smem tile: 144B, 16B-aligned, conflict-free
#define SCALE_F 0.08838834764831843f  // 1/sqrt(128)

// ---------------- scratch (static device memory: allowed) ----------------
__device__ float g_colsum[2][BATCH][16][DIM];
__device__ float g_hbar[2][BATCH][DIM];
__device__ float g_v[2][BATCH][KPT][DIM];
__device__ float g_part[2][BATCH][KPT][NPART][5];
__device__ float g_Y[2][BATCH][KPT][3];

// ---------------- pass 1: column sums of H1/H2 (fp32) ----------------
__global__ void mean_kernel(const float* __restrict__ H1, const float* __restrict__ H2) {
    int chunk = blockIdx.x, b = blockIdx.y, side = blockIdx.z;
    const float* H = side ? H2 : H1;
    int t = threadIdx.x;
    int col4 = t & 31, rl = t >> 5;
    const float4* base = (const float4*)(H + ((size_t)b * NROW + (size_t)chunk * 1024) * DIM);
    float s0 = 0.f, s1 = 0.f, s2 = 0.f, s3 = 0.f;
#pragma unroll 8
    for (int r = rl; r < 1024; r += 8) {
        float4 v = base[(size_t)r * 32 + col4];
        s0 += v.x; s1 += v.y; s2 += v.z; s3 += v.w;
    }
    __shared__ float red[256][4];
    red[t][0] = s0; red[t][1] = s1; red[t][2] = s2; red[t][3] = s3;
    __syncthreads();
    if (t < 32) {
        float a0 = red[t][0], a1 = red[t][1], a2 = red[t][2], a3 = red[t][3];
#pragma unroll
        for (int m = 1; m < 8; m++) {
            a0 += red[t + 32 * m][0]; a1 += red[t + 32 * m][1];
            a2 += red[t + 32 * m][2]; a3 += red[t + 32 * m][3];
        }
        float* o = &g_colsum[side][b][chunk][t * 4];
        o[0] = a0; o[1] = a1; o[2] = a2; o[3] = a3;
    }
}

__global__ void hbar_kernel() {
    int side = blockIdx.x, b = blockIdx.y, d = threadIdx.x;
    float s = 0.f;
#pragma unroll
    for (int c = 0; c < 16; c++) s += g_colsum[side][b][c][d];
    g_hbar[side][b][d] = s * (1.0f / NROW);
}

// v[side][b][k][d] = scale * sum_e W_side[k][d][e] * hbar[side^1][b][e]
__global__ void v_kernel(const float* __restrict__ W1, const float* __restrict__ W2) {
    int k = blockIdx.x, b = blockIdx.y, side = blockIdx.z;
    const float* W = side ? W2 : W1;
    __shared__ float hb[DIM];
    int d = threadIdx.x;
    hb[d] = g_hbar[side ^ 1][b][d];
    __syncthreads();
    const float4* wr = (const float4*)(W + ((size_t)k * DIM + d) * DIM);
    float acc = 0.f;
#pragma unroll 8
    for (int e4 = 0; e4 < 32; e4++) {
        float4 w = __ldg(&wr[e4]);
        acc += w.x * hb[e4 * 4 + 0] + w.y * hb[e4 * 4 + 1]
             + w.z * hb[e4 * 4 + 2] + w.w * hb[e4 * 4 + 3];
    }
    g_v[side][b][k][d] = acc * SCALE_F;
}

// ---------------- pass 2: scores + online softmax + weighted X sums ----------------
union U64F2 { unsigned long long u; float2 f; };

__device__ __forceinline__ void osm_combine(float& m, float& l, float& a0, float& a1, float& a2,
                                            float m2, float l2, float b0, float b1, float b2) {
    float mn = fmaxf(m, m2);
    float f1 = __expf(m - mn), f2 = __expf(m2 - mn);
    m = mn;
    l = l * f1 + l2 * f2;
    a0 = a0 * f1 + b0 * f2;
    a1 = a1 * f1 + b1 * f2;
    a2 = a2 * f1 + b2 * f2;
}

__global__ __launch_bounds__(128, 5) void score_kernel(
    const float* __restrict__ H1, const float* __restrict__ H2,
    const float* __restrict__ X1, const float* __restrict__ X2) {
    int chunk = blockIdx.x, b = blockIdx.y, side = blockIdx.z;
    const float* H = side ? H2 : H1;
    const float* X = side ? X2 : X1;
    int t = threadIdx.x;
    int row0 = chunk * SROWS;

    __shared__ float vs[KPT * DIM];            // 5120 B
    __shared__ float tile[SROWS * TSTRIDE];    // 36864 B  (total 41 KB -> 5 blocks/SM)

    const float* Hb = H + ((size_t)b * NROW + row0) * DIM;

    {   // load v tile into smem (coalesced)
        const float4* vg = (const float4*)&g_v[side][b][0][0];
        float4* vd = (float4*)vs;
        for (int i = t; i < KPT * DIM / 4; i += 128) vd[i] = vg[i];
    }

    unsigned long long accA[KPT], accB[KPT];
#pragma unroll
    for (int k = 0; k < KPT; k++) { accA[k] = 0ull; accB[k] = 0ull; }

#pragma unroll
    for (int c = 0; c < NC; c++) {
        __syncthreads();   // previous chunk's compute done before overwrite (covers v load too)
        // stage 256 rows x 32 cols: coalesced LDG.128 (8 lanes cover a 128B row-segment)
#pragma unroll
        for (int i = 0; i < 16; i++) {
            int idx = t + 128 * i;
            int r = idx >> 3, j = idx & 7;
            float4 val = *(const float4*)(Hb + (size_t)r * DIM + c * CCOLS + j * 4);
            *(float4*)&tile[r * TSTRIDE + j * 4] = val;   // STS.128, conflict-free
        }
        __syncthreads();

        const float* rowA = &tile[t * TSTRIDE];
        const float* rowB = &tile[(t + 128) * TSTRIDE];
        const float* vb = vs + c * CCOLS;
#pragma unroll
        for (int j = 0; j < 8; j++) {
            ulonglong2 xa = *(const ulonglong2*)&rowA[j * 4];   // LDS.128, conflict-free
            ulonglong2 xb = *(const ulonglong2*)&rowB[j * 4];
#pragma unroll
            for (int k = 0; k < KPT; k++) {
                ulonglong2 v = *(const ulonglong2*)&vb[k * DIM + j * 4];  // broadcast LDS.128
                asm("fma.rn.f32x2 %0, %1, %2, %0;" : "+l"(accA[k]) : "l"(xa.x), "l"(v.x));
                asm("fma.rn.f32x2 %0, %1, %2, %0;" : "+l"(accA[k]) : "l"(xa.y), "l"(v.y));
                asm("fma.rn.f32x2 %0, %1, %2, %0;" : "+l"(accB[k]) : "l"(xb.x), "l"(v.x));
                asm("fma.rn.f32x2 %0, %1, %2, %0;" : "+l"(accB[k]) : "l"(xb.y), "l"(v.y));
            }
        }
    }

    // per-thread rows: row0+t and row0+t+128
    const float* Xb = X + ((size_t)b * NROW + row0) * 3;
    float XA0 = Xb[t * 3 + 0], XA1 = Xb[t * 3 + 1], XA2 = Xb[t * 3 + 2];
    float XB0 = Xb[(t + 128) * 3 + 0], XB1 = Xb[(t + 128) * 3 + 1], XB2 = Xb[(t + 128) * 3 + 2];

    int w = t >> 5, lane = t & 31;
#pragma unroll
    for (int k = 0; k < KPT; k++) {
        U64F2 ua, ub;
        ua.u = accA[k]; ub.u = accB[k];
        float sA = ua.f.x + ua.f.y;
        float sB = ub.f.x + ub.f.y;
        float m = fmaxf(sA, sB);
        float eA = __expf(sA - m), eB = __expf(sB - m);
        float l = eA + eB;
        float a0 = eA * XA0 + eB * XB0;
        float a1 = eA * XA1 + eB * XB1;
        float a2 = eA * XA2 + eB * XB2;
#pragma unroll
        for (int off = 16; off > 0; off >>= 1) {
            float m2 = __shfl_xor_sync(0xffffffffu, m, off);
            float l2 = __shfl_xor_sync(0xffffffffu, l, off);
            float b0 = __shfl_xor_sync(0xffffffffu, a0, off);
            float b1 = __shfl_xor_sync(0xffffffffu, a1, off);
            float b2 = __shfl_xor_sync(0xffffffffu, a2, off);
            osm_combine(m, l, a0, a1, a2, m2, l2, b0, b1, b2);
        }
        if (lane == 0) {   // per-warp partial straight to gmem
            float* o = &g_part[side][b][k][chunk * 4 + w][0];
            o[0] = m; o[1] = l; o[2] = a0; o[3] = a1; o[4] = a2;
        }
    }
}

// ---------------- combine partials -> Y ----------------
__global__ void combine_kernel() {
    int side = blockIdx.x, b = blockIdx.y;
    int k = threadIdx.x >> 5, lane = threadIdx.x & 31;
    const float* base = &g_part[side][b][k][0][0];
    const float* p = base + lane * 5;
    float m = p[0], l = p[1], a0 = p[2], a1 = p[3], a2 = p[4];
#pragma unroll
    for (int q = 1; q < NPART / 32; q++) {
        const float* p2 = base + (lane + 32 * q) * 5;
        osm_combine(m, l, a0, a1, a2, p2[0], p2[1], p2[2], p2[3], p2[4]);
    }
#pragma unroll
    for (int off = 16; off > 0; off >>= 1) {
        float m2 = __shfl_xor_sync(0xffffffffu, m, off);
        float l2 = __shfl_xor_sync(0xffffffffu, l, off);
        float b0 = __shfl_xor_sync(0xffffffffu, a0, off);
        float b1 = __shfl_xor_sync(0xffffffffu, a1, off);
        float b2 = __shfl_xor_sync(0xffffffffu, a2, off);
        osm_combine(m, l, a0, a1, a2, m2, l2, b0, b1, b2);
    }
    if (lane == 0) {
        float inv = 1.0f / l;
        g_Y[side][b][k][0] = a0 * inv;
        g_Y[side][b][k][1] = a1 * inv;
        g_Y[side][b][k][2] = a2 * inv;
    }
}

// ---------------- Kabsch (fp32, 3x3 Jacobi) ----------------
__global__ void kabsch_kernel(float* __restrict__ out) {
    int b = threadIdx.x;
    if (b >= BATCH) return;
    float P[KPT][3], Q[KPT][3];
    for (int k = 0; k < KPT; k++)
        for (int c = 0; c < 3; c++) {
            P[k][c] = g_Y[0][b][k][c];
            Q[k][c] = g_Y[1][b][k][c];
        }
    float c1[3] = {0, 0, 0}, c2[3] = {0, 0, 0};
    for (int k = 0; k < KPT; k++)
        for (int c = 0; c < 3; c++) { c1[c] += P[k][c]; c2[c] += Q[k][c]; }
    for (int c = 0; c < 3; c++) { c1[c] *= (1.0f / KPT); c2[c] *= (1.0f / KPT); }

    float Hm[3][3] = {{0,0,0},{0,0,0},{0,0,0}};
    for (int k = 0; k < KPT; k++)
        for (int i = 0; i < 3; i++)
            for (int j = 0; j < 3; j++)
                Hm[i][j] += (P[k][i] - c1[i]) * (Q[k][j] - c2[j]);

    float A[3][3];
    for (int i = 0; i < 3; i++)
        for (int j = 0; j < 3; j++) {
            float s = 0;
            for (int r = 0; r < 3; r++) s += Hm[r][i] * Hm[r][j];
            A[i][j] = s;
        }
    float V[3][3] = {{1,0,0},{0,1,0},{0,0,1}};
    for (int sweep = 0; sweep < 8; sweep++) {
        for (int pq = 0; pq < 3; pq++) {
            int p = (pq == 2) ? 1 : 0;
            int q = (pq == 0) ? 1 : 2;
            float apq = A[p][q];
            if (fabsf(apq) < 1e-35f) continue;
            float theta = (A[q][q] - A[p][p]) / (2.0f * apq);
            float tt = ((theta >= 0.f) ? 1.0f : -1.0f) / (fabsf(theta) + sqrtf(theta * theta + 1.0f));
            float cth = rsqrtf(tt * tt + 1.0f), sth = tt * cth;
            for (int i = 0; i < 3; i++) {
                float aip = A[i][p], aiq = A[i][q];
                A[i][p] = cth * aip - sth * aiq;
                A[i][q] = sth * aip + cth * aiq;
            }
            for (int i = 0; i < 3; i++) {
                float api = A[p][i], aqi = A[q][i];
                A[p][i] = cth * api - sth * aqi;
                A[q][i] = sth * api + cth * aqi;
            }
            for (int i = 0; i < 3; i++) {
                float vip = V[i][p], viq = V[i][q];
                V[i][p] = cth * vip - sth * viq;
                V[i][q] = sth * vip + cth * viq;
            }
        }
    }
    float w[3] = {A[0][0], A[1][1], A[2][2]};
    int idx[3] = {0, 1, 2};
    for (int i = 0; i < 2; i++)
        for (int j = i + 1; j < 3; j++)
            if (w[idx[j]] > w[idx[i]]) { int tmp = idx[i]; idx[i] = idx[j]; idx[j] = tmp; }
    float v0[3], v1[3], v2[3];
    for (int i = 0; i < 3; i++) {
        v0[i] = V[i][idx[0]]; v1[i] = V[i][idx[1]]; v2[i] = V[i][idx[2]];
    }
    float u0[3], u1[3], u2[3];
    for (int i = 0; i < 3; i++) {
        u0[i] = Hm[i][0] * v0[0] + Hm[i][1] * v0[1] + Hm[i][2] * v0[2];
        u1[i] = Hm[i][0] * v1[0] + Hm[i][1] * v1[1] + Hm[i][2] * v1[2];
    }
    float n0 = sqrtf(u0[0]*u0[0] + u0[1]*u0[1] + u0[2]*u0[2]);
    n0 = (n0 > 0.f) ? 1.0f / n0 : 0.0f;
    for (int i = 0; i < 3; i++) u0[i] *= n0;
    float d01 = u1[0]*u0[0] + u1[1]*u0[1] + u1[2]*u0[2];
    for (int i = 0; i < 3; i++) u1[i] -= d01 * u0[i];
    float n1 = sqrtf(u1[0]*u1[0] + u1[1]*u1[1] + u1[2]*u1[2]);
    n1 = (n1 > 0.f) ? 1.0f / n1 : 0.0f;
    for (int i = 0; i < 3; i++) u1[i] *= n1;
    u2[0] = u0[1]*u1[2] - u0[2]*u1[1];
    u2[1] = u0[2]*u1[0] - u0[0]*u1[2];
    u2[2] = u0[0]*u1[1] - u0[1]*u1[0];
    float cx = v1[1]*v2[2] - v1[2]*v2[1];
    float cy = v1[2]*v2[0] - v1[0]*v2[2];
    float cz = v1[0]*v2[1] - v1[1]*v2[0];
    float detV = v0[0]*cx + v0[1]*cy + v0[2]*cz;
    float s = (detV >= 0.f) ? 1.0f : -1.0f;

    float R[3][3];
    for (int i = 0; i < 3; i++)
        for (int j = 0; j < 3; j++)
            R[i][j] = u0[i]*v0[j] + u1[i]*v1[j] + s*u2[i]*v2[j];
    float tv[3];
    for (int j = 0; j < 3; j++)
        tv[j] = c2[j] - (c1[0]*R[0][j] + c1[1]*R[1][j] + c1[2]*R[2][j]);

    float* ob = out + b * 90;   // [3][K][3]
    for (int k = 0; k < KPT; k++)
        for (int c = 0; c < 3; c++) {
            ob[0 * 30 + k * 3 + c] = P[k][c];
            ob[1 * 30 + k * 3 + c] = Q[k][c];
        }
    for (int k = 0; k < KPT; k++)
        for (int j = 0; j < 3; j++) {
            float y = P[k][0]*R[0][j] + P[k][1]*R[1][j] + P[k][2]*R[2][j] + tv[j];
            ob[2 * 30 + k * 3 + j] = y;
        }
}

// ---------------- launch ----------------
extern "C" void kernel_launch(void* const* d_in, const int* in_sizes, int n_in,
                              void* d_out, int out_size) {
    const float* H1 = (const float*)d_in[0];
    const float* H2 = (const float*)d_in[1];
    const float* X1 = (const float*)d_in[2];
    const float* X2 = (const float*)d_in[3];
    const float* W1 = (const float*)d_in[4];
    const float* W2 = (const float*)d_in[5];
    float* out = (float*)d_out;

    mean_kernel<<<dim3(16, BATCH, 2), 256>>>(H1, H2);
    hbar_kernel<<<dim3(2, BATCH), DIM>>>();
    v_kernel<<<dim3(KPT, BATCH, 2), DIM>>>(W1, W2);
    score_kernel<<<dim3(NBLK, BATCH, 2), 128>>>(H1, H2, X1, X2);
    combine_kernel<<<dim3(2, BATCH), 320>>>();
    kabsch_kernel<<<1, 32>>>(out);
}

// round 8
// speedup vs baseline: 1.4098x; 1.2543x over previous
#include <cuda_runtime.h>

#define BATCH 16
#define NROW  16384
#define DIM   128
#define KPT   10
#define SROWS 256                 // rows per score block
#define NBLK  64                  // 16384 / 256
#define MCH   32                  // mean-kernel chunks (512 rows each)
#define SCALE_F 0.08838834764831843f  // 1/sqrt(128)

// ---------------- scratch (static device memory: allowed) ----------------
// g_cs[side][b][chunk][d] column-sum partials: side1 from mean (32 chunks),
// side0 fused into score pass (64 chunks)
__device__ float g_cs[2][BATCH][NBLK][DIM];
__device__ float g_v[2][BATCH][KPT][DIM];
__device__ float g_part[2][BATCH][KPT][NBLK][5];
__device__ float g_Y[2][BATCH][KPT][3];

// ---------------- pass 1: column sums of H2 only ----------------
__global__ void mean_kernel(const float* __restrict__ H2) {
    int chunk = blockIdx.x, b = blockIdx.y;
    int t = threadIdx.x;
    int col4 = t & 31, rl = t >> 5;
    const float4* base = (const float4*)(H2 + ((size_t)b * NROW + (size_t)chunk * 512) * DIM);
    float s0 = 0.f, s1 = 0.f, s2 = 0.f, s3 = 0.f;
#pragma unroll 8
    for (int r = rl; r < 512; r += 8) {
        float4 v = base[(size_t)r * 32 + col4];
        s0 += v.x; s1 += v.y; s2 += v.z; s3 += v.w;
    }
    __shared__ float red[256][4];
    red[t][0] = s0; red[t][1] = s1; red[t][2] = s2; red[t][3] = s3;
    __syncthreads();
    if (t < 32) {
        float a0 = red[t][0], a1 = red[t][1], a2 = red[t][2], a3 = red[t][3];
#pragma unroll
        for (int m = 1; m < 8; m++) {
            a0 += red[t + 32 * m][0]; a1 += red[t + 32 * m][1];
            a2 += red[t + 32 * m][2]; a3 += red[t + 32 * m][3];
        }
        float* o = &g_cs[1][b][chunk][t * 4];
        o[0] = a0; o[1] = a1; o[2] = a2; o[3] = a3;
    }
}

// ---------------- fused hbar + v ----------------
// v[side][b][k][d] = scale * sum_e W_side[k][d][e] * hbar[side^1][b][e]
// hbar[side^1] reduced on the fly from g_cs[side^1] (nch chunks)
__global__ void v_kernel(const float* __restrict__ W, int side, int nch) {
    int k = blockIdx.x, b = blockIdx.y;
    __shared__ float hb[DIM];
    int d = threadIdx.x;
    {
        float s = 0.f;
        const float* cs = &g_cs[side ^ 1][b][0][d];
        for (int c = 0; c < nch; c++) s += cs[c * DIM];
        hb[d] = s * (1.0f / NROW);
    }
    __syncthreads();
    const float4* wr = (const float4*)(W + ((size_t)k * DIM + d) * DIM);
    float acc = 0.f;
#pragma unroll 8
    for (int e4 = 0; e4 < 32; e4++) {
        float4 w = __ldg(&wr[e4]);
        acc += w.x * hb[e4 * 4 + 0] + w.y * hb[e4 * 4 + 1]
             + w.z * hb[e4 * 4 + 2] + w.w * hb[e4 * 4 + 3];
    }
    g_v[side][b][k][d] = acc * SCALE_F;
}

// ---------------- pass 2: scores + online softmax (+ fused colsum on side 0) ----------------
union U64F2 { unsigned long long u; float2 f; };

__device__ __forceinline__ void osm_combine(float& m, float& l, float& a0, float& a1, float& a2,
                                            float m2, float l2, float b0, float b1, float b2) {
    float mn = fmaxf(m, m2);
    float f1 = __expf(m - mn), f2 = __expf(m2 - mn);
    m = mn;
    l = l * f1 + l2 * f2;
    a0 = a0 * f1 + b0 * f2;
    a1 = a1 * f1 + b1 * f2;
    a2 = a2 * f1 + b2 * f2;
}

__global__ __launch_bounds__(128, 4) void score_kernel(
    const float* __restrict__ H, const float* __restrict__ X, int side) {
    int chunk = blockIdx.x, b = blockIdx.y;
    int t = threadIdx.x;
    int row0 = chunk * SROWS;

    __shared__ float vs[KPT * DIM];       // 5120 B
    __shared__ float tile[SROWS * 38];    // 38912 B, stride 38 -> conflict-free LDS.64
    __shared__ float red[4][KPT][5];      // 800 B
    __shared__ float csum[4][32];         // 512 B

    {   // load v tile (coalesced)
        const float4* vg = (const float4*)&g_v[side][b][0][0];
        float4* vd = (float4*)vs;
        for (int i = t; i < KPT * DIM / 4; i += 128) vd[i] = vg[i];
    }

    unsigned long long accA[KPT], accB[KPT];
#pragma unroll
    for (int k = 0; k < KPT; k++) { accA[k] = 0ull; accB[k] = 0ull; }

    const float* Hb = H + ((size_t)b * NROW + row0) * DIM;

    for (int c = 0; c < 4; c++) {
        __syncthreads();
        // stage 256 rows x 32 floats (chunk c of d) into smem, coalesced LDG.128
#pragma unroll
        for (int i = 0; i < 16; i++) {
            int t2 = t + 128 * i;
            int r = t2 >> 3, j = t2 & 7;
            float4 val = *(const float4*)(Hb + (size_t)r * DIM + c * 32 + j * 4);
            float* dst = &tile[r * 38 + j * 4];
            *(float2*)dst = make_float2(val.x, val.y);
            *(float2*)(dst + 2) = make_float2(val.z, val.w);
        }
        __syncthreads();
        const unsigned long long* rowA = (const unsigned long long*)&tile[t * 38];
        const unsigned long long* rowB = (const unsigned long long*)&tile[(t + 128) * 38];
#pragma unroll
        for (int j = 0; j < 16; j++) {
            unsigned long long xA = rowA[j], xB = rowB[j];
#pragma unroll
            for (int k = 0; k < KPT; k++) {
                unsigned long long v = *(const unsigned long long*)&vs[k * DIM + c * 32 + 2 * j];
                asm("fma.rn.f32x2 %0, %1, %2, %0;" : "+l"(accA[k]) : "l"(xA), "l"(v));
                asm("fma.rn.f32x2 %0, %1, %2, %0;" : "+l"(accB[k]) : "l"(xB), "l"(v));
            }
        }
        if (side == 0) {
            // fused column sums of this tile chunk (cols c*32 .. c*32+31)
            int col = t & 31, q = t >> 5;
            float s = 0.f;
            int rbase = q * 64;
#pragma unroll 8
            for (int r = 0; r < 64; r++) s += tile[(rbase + r) * 38 + col];
            csum[q][col] = s;
            __syncthreads();
            if (t < 32)
                g_cs[0][b][chunk][c * 32 + t] = csum[0][t] + csum[1][t] + csum[2][t] + csum[3][t];
        }
    }

    // per-thread rows: row0+t and row0+t+128
    const float* Xb = X + ((size_t)b * NROW + row0) * 3;
    float XA0 = Xb[t * 3 + 0], XA1 = Xb[t * 3 + 1], XA2 = Xb[t * 3 + 2];
    float XB0 = Xb[(t + 128) * 3 + 0], XB1 = Xb[(t + 128) * 3 + 1], XB2 = Xb[(t + 128) * 3 + 2];

    int w = t >> 5, lane = t & 31;
#pragma unroll
    for (int k = 0; k < KPT; k++) {
        U64F2 ua, ub;
        ua.u = accA[k]; ub.u = accB[k];
        float sA = ua.f.x + ua.f.y;
        float sB = ub.f.x + ub.f.y;
        float m = fmaxf(sA, sB);
        float eA = __expf(sA - m), eB = __expf(sB - m);
        float l = eA + eB;
        float a0 = eA * XA0 + eB * XB0;
        float a1 = eA * XA1 + eB * XB1;
        float a2 = eA * XA2 + eB * XB2;
#pragma unroll
        for (int off = 16; off > 0; off >>= 1) {
            float m2 = __shfl_xor_sync(0xffffffffu, m, off);
            float l2 = __shfl_xor_sync(0xffffffffu, l, off);
            float b0 = __shfl_xor_sync(0xffffffffu, a0, off);
            float b1 = __shfl_xor_sync(0xffffffffu, a1, off);
            float b2 = __shfl_xor_sync(0xffffffffu, a2, off);
            osm_combine(m, l, a0, a1, a2, m2, l2, b0, b1, b2);
        }
        if (lane == 0) {
            red[w][k][0] = m; red[w][k][1] = l;
            red[w][k][2] = a0; red[w][k][3] = a1; red[w][k][4] = a2;
        }
    }
    __syncthreads();
    if (t < KPT) {
        float m = red[0][t][0], l = red[0][t][1];
        float a0 = red[0][t][2], a1 = red[0][t][3], a2 = red[0][t][4];
#pragma unroll
        for (int w2 = 1; w2 < 4; w2++)
            osm_combine(m, l, a0, a1, a2,
                        red[w2][t][0], red[w2][t][1], red[w2][t][2], red[w2][t][3], red[w2][t][4]);
        float* o = &g_part[side][b][t][chunk][0];
        o[0] = m; o[1] = l; o[2] = a0; o[3] = a1; o[4] = a2;
    }
}

// ---------------- combine partials -> Y ----------------
__global__ void combine_kernel() {
    int side = blockIdx.x, b = blockIdx.y;
    int k = threadIdx.x >> 5, lane = threadIdx.x & 31;
    const float* base = &g_part[side][b][k][0][0];
    const float* p0 = base + lane * 5;
    const float* p1 = base + (lane + 32) * 5;
    float m = p0[0], l = p0[1], a0 = p0[2], a1 = p0[3], a2 = p0[4];
    osm_combine(m, l, a0, a1, a2, p1[0], p1[1], p1[2], p1[3], p1[4]);
#pragma unroll
    for (int off = 16; off > 0; off >>= 1) {
        float m2 = __shfl_xor_sync(0xffffffffu, m, off);
        float l2 = __shfl_xor_sync(0xffffffffu, l, off);
        float b0 = __shfl_xor_sync(0xffffffffu, a0, off);
        float b1 = __shfl_xor_sync(0xffffffffu, a1, off);
        float b2 = __shfl_xor_sync(0xffffffffu, a2, off);
        osm_combine(m, l, a0, a1, a2, m2, l2, b0, b1, b2);
    }
    if (lane == 0) {
        float inv = 1.0f / l;
        g_Y[side][b][k][0] = a0 * inv;
        g_Y[side][b][k][1] = a1 * inv;
        g_Y[side][b][k][2] = a2 * inv;
    }
}

// ---------------- Kabsch (fp32, 3x3 Jacobi) ----------------
__global__ void kabsch_kernel(float* __restrict__ out) {
    int b = threadIdx.x;
    if (b >= BATCH) return;
    float P[KPT][3], Q[KPT][3];
    for (int k = 0; k < KPT; k++)
        for (int c = 0; c < 3; c++) {
            P[k][c] = g_Y[0][b][k][c];
            Q[k][c] = g_Y[1][b][k][c];
        }
    float c1[3] = {0, 0, 0}, c2[3] = {0, 0, 0};
    for (int k = 0; k < KPT; k++)
        for (int c = 0; c < 3; c++) { c1[c] += P[k][c]; c2[c] += Q[k][c]; }
    for (int c = 0; c < 3; c++) { c1[c] *= (1.0f / KPT); c2[c] *= (1.0f / KPT); }

    float Hm[3][3] = {{0,0,0},{0,0,0},{0,0,0}};
    for (int k = 0; k < KPT; k++)
        for (int i = 0; i < 3; i++)
            for (int j = 0; j < 3; j++)
                Hm[i][j] += (P[k][i] - c1[i]) * (Q[k][j] - c2[j]);

    float A[3][3];
    for (int i = 0; i < 3; i++)
        for (int j = 0; j < 3; j++) {
            float s = 0;
            for (int r = 0; r < 3; r++) s += Hm[r][i] * Hm[r][j];
            A[i][j] = s;
        }
    float V[3][3] = {{1,0,0},{0,1,0},{0,0,1}};
    for (int sweep = 0; sweep < 8; sweep++) {
        for (int pq = 0; pq < 3; pq++) {
            int p = (pq == 2) ? 1 : 0;
            int q = (pq == 0) ? 1 : 2;
            float apq = A[p][q];
            if (fabsf(apq) < 1e-35f) continue;
            float theta = (A[q][q] - A[p][p]) / (2.0f * apq);
            float tt = ((theta >= 0.f) ? 1.0f : -1.0f) / (fabsf(theta) + sqrtf(theta * theta + 1.0f));
            float cth = rsqrtf(tt * tt + 1.0f), sth = tt * cth;
            for (int i = 0; i < 3; i++) {
                float aip = A[i][p], aiq = A[i][q];
                A[i][p] = cth * aip - sth * aiq;
                A[i][q] = sth * aip + cth * aiq;
            }
            for (int i = 0; i < 3; i++) {
                float api = A[p][i], aqi = A[q][i];
                A[p][i] = cth * api - sth * aqi;
                A[q][i] = sth * api + cth * aqi;
            }
            for (int i = 0; i < 3; i++) {
                float vip = V[i][p], viq = V[i][q];
                V[i][p] = cth * vip - sth * viq;
                V[i][q] = sth * vip + cth * viq;
            }
        }
    }
    float w[3] = {A[0][0], A[1][1], A[2][2]};
    int idx[3] = {0, 1, 2};
    for (int i = 0; i < 2; i++)
        for (int j = i + 1; j < 3; j++)
            if (w[idx[j]] > w[idx[i]]) { int tmp = idx[i]; idx[i] = idx[j]; idx[j] = tmp; }
    float v0[3], v1[3], v2[3];
    for (int i = 0; i < 3; i++) {
        v0[i] = V[i][idx[0]]; v1[i] = V[i][idx[1]]; v2[i] = V[i][idx[2]];
    }
    float u0[3], u1[3], u2[3];
    for (int i = 0; i < 3; i++) {
        u0[i] = Hm[i][0] * v0[0] + Hm[i][1] * v0[1] + Hm[i][2] * v0[2];
        u1[i] = Hm[i][0] * v1[0] + Hm[i][1] * v1[1] + Hm[i][2] * v1[2];
    }
    float n0 = sqrtf(u0[0]*u0[0] + u0[1]*u0[1] + u0[2]*u0[2]);
    n0 = (n0 > 0.f) ? 1.0f / n0 : 0.0f;
    for (int i = 0; i < 3; i++) u0[i] *= n0;
    float d01 = u1[0]*u0[0] + u1[1]*u0[1] + u1[2]*u0[2];
    for (int i = 0; i < 3; i++) u1[i] -= d01 * u0[i];
    float n1 = sqrtf(u1[0]*u1[0] + u1[1]*u1[1] + u1[2]*u1[2]);
    n1 = (n1 > 0.f) ? 1.0f / n1 : 0.0f;
    for (int i = 0; i < 3; i++) u1[i] *= n1;
    u2[0] = u0[1]*u1[2] - u0[2]*u1[1];
    u2[1] = u0[2]*u1[0] - u0[0]*u1[2];
    u2[2] = u0[0]*u1[1] - u0[1]*u1[0];
    float cx = v1[1]*v2[2] - v1[2]*v2[1];
    float cy = v1[2]*v2[0] - v1[0]*v2[2];
    float cz = v1[0]*v2[1] - v1[1]*v2[0];
    float detV = v0[0]*cx + v0[1]*cy + v0[2]*cz;
    float s = (detV >= 0.f) ? 1.0f : -1.0f;

    float R[3][3];
    for (int i = 0; i < 3; i++)
        for (int j = 0; j < 3; j++)
            R[i][j] = u0[i]*v0[j] + u1[i]*v1[j] + s*u2[i]*v2[j];
    float tv[3];
    for (int j = 0; j < 3; j++)
        tv[j] = c2[j] - (c1[0]*R[0][j] + c1[1]*R[1][j] + c1[2]*R[2][j]);

    float* ob = out + b * 90;   // [3][K][3]
    for (int k = 0; k < KPT; k++)
        for (int c = 0; c < 3; c++) {
            ob[0 * 30 + k * 3 + c] = P[k][c];
            ob[1 * 30 + k * 3 + c] = Q[k][c];
        }
    for (int k = 0; k < KPT; k++)
        for (int j = 0; j < 3; j++) {
            float y = P[k][0]*R[0][j] + P[k][1]*R[1][j] + P[k][2]*R[2][j] + tv[j];
            ob[2 * 30 + k * 3 + j] = y;
        }
}

// ---------------- launch ----------------
extern "C" void kernel_launch(void* const* d_in, const int* in_sizes, int n_in,
                              void* d_out, int out_size) {
    const float* H1 = (const float*)d_in[0];
    const float* H2 = (const float*)d_in[1];
    const float* X1 = (const float*)d_in[2];
    const float* X2 = (const float*)d_in[3];
    const float* W1 = (const float*)d_in[4];
    const float* W2 = (const float*)d_in[5];
    float* out = (float*)d_out;

    // pass 1: column sums of H2 (128 MB)
    mean_kernel<<<dim3(MCH, BATCH), 256>>>(H2);
    // v1 = W1 @ mean(H2)
    v_kernel<<<dim3(KPT, BATCH), DIM>>>(W1, 0, MCH);
    // pass 2: side-0 scores over H1 + fused column sums of H1 (128 MB)
    score_kernel<<<dim3(NBLK, BATCH), 128>>>(H1, X1, 0);
    // v2 = W2 @ mean(H1)  (from score-pass partials, 64 chunks)
    v_kernel<<<dim3(KPT, BATCH), DIM>>>(W2, 1, NBLK);
    // pass 3: side-1 scores over H2 (128 MB)
    score_kernel<<<dim3(NBLK, BATCH), 128>>>(H2, X2, 1);
    combine_kernel<<<dim3(2, BATCH), 320>>>();
    kabsch_kernel<<<1, 32>>>(out);
}